// round 6
// baseline (speedup 1.0000x reference)
#include <cuda_runtime.h>
#include <cstdint>

#define B_  64
#define S_  2048
#define D_  256
#define V_  256
#define L_  4
#define M_  (B_*S_)      // 131072
#define G3  (3*D_)       // 768

// ---------------- scratch (device globals; allocation-free) ----------------
__device__ __align__(16) float g_seqA[(size_t)M_*D_];
__device__ __align__(16) float g_seqB[(size_t)M_*D_];
__device__ __align__(16) float g_gi  [(size_t)M_*G3];

typedef unsigned long long u64;

__device__ __forceinline__ u64 pk(float x, float y){
    u64 r; asm("mov.b64 %0,{%1,%2};" : "=l"(r) : "f"(x), "f"(y)); return r;
}
__device__ __forceinline__ void fma2(u64 &a, u64 b, u64 c){
    asm("fma.rn.f32x2 %0,%1,%2,%0;" : "+l"(a) : "l"(b), "l"(c));
}
__device__ __forceinline__ float2 up(u64 v){
    float2 f; asm("mov.b64 {%0,%1},%2;" : "=f"(f.x), "=f"(f.y) : "l"(v)); return f;
}

// ---------------- embedding gather ----------------
__global__ void embed_k(const int* __restrict__ x, const float* __restrict__ emb){
    int t = blockIdx.x*256 + threadIdx.x;          // float4 index over M_*64
    int m = t >> 6, d4 = t & 63;
    int tok = __ldg(&x[m]);
    ((float4*)g_seqA)[(size_t)m*64 + d4] = ((const float4*)emb)[(size_t)tok*64 + d4];
}

// ---------------- C[M,N] = A[M,256] * Bw[N,256]^T + bias ----------------
__global__ __launch_bounds__(256,2)
void gemm_tn(int asel, const float* __restrict__ Bw, const float* __restrict__ bias,
             float* __restrict__ Cext, int csel, int N){
    __shared__ float As[16][128];
    __shared__ float Bs[16][128];
    const float* A = asel ? g_seqB : g_seqA;
    float*       C = csel ? Cext  : g_gi;

    const int nt = N >> 7;
    const int by = blockIdx.x / nt, bx = blockIdx.x % nt;
    const int m0 = by << 7, n0 = bx << 7;
    const int t  = threadIdx.x, tx = t & 15, ty = t >> 4;
    const int lr = t >> 2, lc = (t & 3) << 2;

    const float* Ap = A  + (size_t)(m0 + lr)*256 + lc;
    const float* Bp = Bw + (size_t)(n0 + lr)*256 + lc;

    u64 acc[4][8];
    #pragma unroll
    for (int i = 0; i < 4; i++)
        #pragma unroll
        for (int j = 0; j < 8; j++) acc[i][j] = 0ull;

    for (int kb = 0; kb < 256; kb += 16){
        float4 a0 = *(const float4*)(Ap + kb);
        float4 a1 = *(const float4*)(Ap + (size_t)64*256 + kb);
        float4 b0 = *(const float4*)(Bp + kb);
        float4 b1 = *(const float4*)(Bp + (size_t)64*256 + kb);
        As[lc+0][lr]    = a0.x; As[lc+1][lr]    = a0.y; As[lc+2][lr]    = a0.z; As[lc+3][lr]    = a0.w;
        As[lc+0][lr+64] = a1.x; As[lc+1][lr+64] = a1.y; As[lc+2][lr+64] = a1.z; As[lc+3][lr+64] = a1.w;
        Bs[lc+0][lr]    = b0.x; Bs[lc+1][lr]    = b0.y; Bs[lc+2][lr]    = b0.z; Bs[lc+3][lr]    = b0.w;
        Bs[lc+0][lr+64] = b1.x; Bs[lc+1][lr+64] = b1.y; Bs[lc+2][lr+64] = b1.z; Bs[lc+3][lr+64] = b1.w;
        __syncthreads();
        #pragma unroll
        for (int k = 0; k < 16; k++){
            float4 av0 = *(const float4*)&As[k][ty*8];
            float4 av1 = *(const float4*)&As[k][ty*8+4];
            float4 bv0 = *(const float4*)&Bs[k][tx*8];
            float4 bv1 = *(const float4*)&Bs[k][tx*8+4];
            u64 ap[4] = { pk(av0.x,av0.y), pk(av0.z,av0.w), pk(av1.x,av1.y), pk(av1.z,av1.w) };
            u64 bd[8] = { pk(bv0.x,bv0.x), pk(bv0.y,bv0.y), pk(bv0.z,bv0.z), pk(bv0.w,bv0.w),
                          pk(bv1.x,bv1.x), pk(bv1.y,bv1.y), pk(bv1.z,bv1.z), pk(bv1.w,bv1.w) };
            #pragma unroll
            for (int i = 0; i < 4; i++)
                #pragma unroll
                for (int j = 0; j < 8; j++) fma2(acc[i][j], ap[i], bd[j]);
        }
        __syncthreads();
    }

    float bv[8];
    #pragma unroll
    for (int j = 0; j < 8; j++) bv[j] = __ldg(&bias[n0 + tx*8 + j]);
    #pragma unroll
    for (int i = 0; i < 4; i++){
        float c0[8], c1[8];
        #pragma unroll
        for (int j = 0; j < 8; j++){
            float2 f = up(acc[i][j]);
            c0[j] = f.x + bv[j];
            c1[j] = f.y + bv[j];
        }
        float* Cp0 = C + (size_t)(m0 + ty*8 + 2*i)*N + n0 + tx*8;
        float* Cp1 = Cp0 + N;
        ((float4*)Cp0)[0] = make_float4(c0[0],c0[1],c0[2],c0[3]);
        ((float4*)Cp0)[1] = make_float4(c0[4],c0[5],c0[6],c0[7]);
        ((float4*)Cp1)[0] = make_float4(c1[0],c1[1],c1[2],c1[3]);
        ((float4*)Cp1)[1] = make_float4(c1[4],c1[5],c1[6],c1[7]);
    }
}

// ---------------- recurrent scan: 16 clusters x 8 CTAs ----------------
// cluster = batch group (4 batch); CTA rank = d-group (32 dims -> 96 Wh rows).
// 384 threads: rr = tid%96 (gate row), kq = tid/96 (k-quarter, 64 k each).
// h lives in every CTA's SMEM (double-buffered); after gate math each gate
// thread broadcasts its h value to all 8 ranks via st.shared::cluster; one
// cluster barrier per step.
#define WP_OFF   0                      // 96 rows x 64 float4 = 24576 floats
#define HS_OFF   24576                  // 2 x [4 b][256 k]     = 2048 floats
#define GHP_OFF  (24576 + 2048)         // [4 kq][96 rr] x 5pad = 1920 floats
#define BH_OFF   (GHP_OFF + 1920)       // 96 floats
#define SCAN_SMEM_BYTES ((BH_OFF + 96) * 4)   // 114,560 B

__global__ __launch_bounds__(384,1) __cluster_dims__(8,1,1)
void gru_scan(const float* __restrict__ Wh, const float* __restrict__ bh, int dsel){
    extern __shared__ float sm[];
    float* WP  = sm + WP_OFF;
    float* HS  = sm + HS_OFF;
    float* GHP = sm + GHP_OFF;
    float* BH  = sm + BH_OFF;
    float* out = dsel ? g_seqB : g_seqA;

    const int tid = threadIdx.x;
    const int bg  = blockIdx.x >> 3;     // cluster index (batch group)
    const int dg  = blockIdx.x & 7;      // == cluster ctarank (d-group)

    // W_hh slice -> SMEM, layout WP[(k4*96 + rr)*4 + j] (f32x2-pair friendly)
    for (int idx = tid; idx < 96*64; idx += 384){
        int rr = idx >> 6, k4 = idx & 63;
        int grow = (rr >> 5)*256 + dg*32 + (rr & 31);
        *(float4*)&WP[(k4*96 + rr)*4] = *(const float4*)&Wh[(size_t)grow*256 + k4*4];
    }
    if (tid < 96) BH[tid] = bh[(tid >> 5)*256 + dg*32 + (tid & 31)];
    for (int i = tid; i < 2048; i += 384) HS[i] = 0.f;     // both h buffers

    const int  rr = tid % 96, kq = tid / 96;
    const int  gb = tid >> 5, gd = tid & 31;               // gate identity
    const bool isGate = tid < 128;
    const size_t giBase  = (size_t)(bg*4 + gb)*S_*G3 + dg*32 + gd;
    const size_t outBase = (size_t)(bg*4 + gb)*S_*D_ + dg*32 + gd;

    // Hoisted DSMEM addresses of my h slot in every rank (both buffers)
    uint32_t ra0[8], ra1[8];
    {
        uint32_t l0 = (uint32_t)__cvta_generic_to_shared(&HS[gb*256 + dg*32 + gd]);
        uint32_t l1 = l0 + 1024*4;
        #pragma unroll
        for (int rk = 0; rk < 8; rk++){
            asm("mapa.shared::cluster.u32 %0, %1, %2;" : "=r"(ra0[rk]) : "r"(l0), "r"(rk));
            asm("mapa.shared::cluster.u32 %0, %1, %2;" : "=r"(ra1[rk]) : "r"(l1), "r"(rk));
        }
    }
    __syncthreads();
    asm volatile("barrier.cluster.arrive.aligned;" ::: "memory");
    asm volatile("barrier.cluster.wait.aligned;"   ::: "memory");

    for (int t = 0; t < S_; t++){
        const float* hcur = HS + (t & 1)*1024;

        // prefetch this step's input-side gates (hidden under the dot products)
        float gir = 0.f, giz = 0.f, gin = 0.f;
        if (isGate){
            const float* gp = g_gi + giBase + (size_t)t*G3;
            gir = __ldg(gp); giz = __ldg(gp + D_); gin = __ldg(gp + 2*D_);
        }

        // gh partials over my k-quarter: accumulate along k-pairs (no pk ops)
        u64 a0 = 0ull, a1 = 0ull, a2 = 0ull, a3 = 0ull;
        #pragma unroll
        for (int i = 0; i < 16; i++){
            const int k4 = kq*16 + i;
            ulonglong2 wv = *(const ulonglong2*)&WP[(k4*96 + rr)*4];
            ulonglong2 h0 = *(const ulonglong2*)&hcur[        k4*4];
            ulonglong2 h1 = *(const ulonglong2*)&hcur[256  +  k4*4];
            ulonglong2 h2 = *(const ulonglong2*)&hcur[512  +  k4*4];
            ulonglong2 h3 = *(const ulonglong2*)&hcur[768  +  k4*4];
            fma2(a0, wv.x, h0.x);  fma2(a0, wv.y, h0.y);
            fma2(a1, wv.x, h1.x);  fma2(a1, wv.y, h1.y);
            fma2(a2, wv.x, h2.x);  fma2(a2, wv.y, h2.y);
            fma2(a3, wv.x, h3.x);  fma2(a3, wv.y, h3.y);
        }
        {
            float2 f0 = up(a0), f1 = up(a1), f2 = up(a2), f3 = up(a3);
            int gp4 = (kq*96 + rr)*5;                 // stride-5 pad: bank-free
            GHP[gp4+0] = f0.x + f0.y;
            GHP[gp4+1] = f1.x + f1.y;
            GHP[gp4+2] = f2.x + f2.y;
            GHP[gp4+3] = f3.x + f3.y;
        }
        __syncthreads();

        if (isGate){
            float ghr = 0.f, ghz = 0.f, ghn = 0.f;
            #pragma unroll
            for (int q = 0; q < 4; q++){
                ghr += GHP[(q*96 +      gd)*5 + gb];
                ghz += GHP[(q*96 + 32 + gd)*5 + gb];
                ghn += GHP[(q*96 + 64 + gd)*5 + gb];
            }
            float hold = hcur[gb*256 + dg*32 + gd];
            float r  = 1.f/(1.f + __expf(-(gir + ghr + BH[gd])));
            float z  = 1.f/(1.f + __expf(-(giz + ghz + BH[32+gd])));
            float nx = gin + r*(ghn + BH[64+gd]);
            float e2 = __expf(-2.f*nx);
            float n_ = (1.f - e2)/(1.f + e2);
            float hn = (1.f - z)*n_ + z*hold;
            out[outBase + (size_t)t*D_] = hn;
            // broadcast h_new into next-step buffer of all 8 ranks
            #pragma unroll
            for (int rk = 0; rk < 8; rk++){
                uint32_t ad = (t & 1) ? ra0[rk] : ra1[rk];
                asm volatile("st.shared::cluster.f32 [%0], %1;"
                             :: "r"(ad), "f"(hn) : "memory");
            }
        }
        // arrive(release) orders the DSMEM stores; wait makes them visible
        asm volatile("barrier.cluster.arrive.aligned;" ::: "memory");
        asm volatile("barrier.cluster.wait.aligned;"   ::: "memory");
    }
}

// ---------------- launch ----------------
extern "C" void kernel_launch(void* const* d_in, const int* in_sizes, int n_in,
                              void* d_out, int out_size){
    const int*   x     = (const int*)  d_in[0];
    const float* emb   = (const float*)d_in[1];
    const float* W_ih  = (const float*)d_in[2];
    const float* W_hh  = (const float*)d_in[3];
    const float* b_ih  = (const float*)d_in[4];
    const float* b_hh  = (const float*)d_in[5];
    const float* W_out = (const float*)d_in[6];
    const float* b_out = (const float*)d_in[7];
    float* out = (float*)d_out;

    cudaFuncSetAttribute(gru_scan, cudaFuncAttributeMaxDynamicSharedMemorySize,
                         SCAN_SMEM_BYTES);

    embed_k<<<(M_*64)/256, 256>>>(x, emb);

    for (int l = 0; l < L_; l++){
        int asel = l & 1;              // layer input: A,B,A,B
        gemm_tn<<<(M_/128)*(G3/128), 256>>>(asel, W_ih + (size_t)l*G3*D_,
                                            b_ih + (size_t)l*G3, nullptr, 0, G3);
        gru_scan<<<128, 384, SCAN_SMEM_BYTES>>>(W_hh + (size_t)l*G3*D_,
                                                b_hh + (size_t)l*G3, asel ^ 1);
    }
    gemm_tn<<<(M_/128)*(V_/128), 256>>>(0, W_out, b_out, out, 1, V_);
}